// round 12
// baseline (speedup 1.0000x reference)
#include <cuda_runtime.h>
#include <cuda_bf16.h>

#define HH   128
#define GG   512          // 4*H
#define TT   512
#define BB   512
#define KIN  18
#define BT   4            // batches per CTA
#define NBLK (BB / BT)

#define ZLEN   160        // z stride per batch
#define NJ0    10         // j-chunks per slice, layer0 (40 k's: uneven h/x mix, uniform 40 slices)
#define NJ1    8          // j-chunks per slice, layer1 (32 k's)
#define W0_E4  (NJ0 * 2)  // uint4 weight entries per thread, layer0 (16 reg + 4 smem)
#define W1_E4  (NJ1 * 2)  // all 16 in registers

typedef unsigned long long u64;

// static scratch (no allocation allowed in kernel_launch)
__device__ float g_h1[(size_t)BB * TT * HH];     // layer0 hidden
__device__ float g_xp1[(size_t)BB * TT * GG];    // layer1 input proj

// ---- packed fp32x2 helpers (SASS FFMA2; only reachable via PTX) ----
__device__ __forceinline__ u64 pack2(float lo, float hi) {
    u64 r; asm("mov.b64 %0, {%1, %2};" : "=l"(r) : "f"(lo), "f"(hi)); return r;
}
__device__ __forceinline__ float2 unpack2(u64 v) {
    float2 r; asm("mov.b64 {%0, %1}, %2;" : "=f"(r.x), "=f"(r.y) : "l"(v)); return r;
}
__device__ __forceinline__ void fma2(u64& d, u64 a, u64 b) {
    asm("fma.rn.f32x2 %0, %1, %2, %0;" : "+l"(d) : "l"(a), "l"(b));
}
// two bf16 weights packed in one u32 -> f32x2 pair, pure ALU (no F2F)
__device__ __forceinline__ u64 bfpair(unsigned v) {
    unsigned lo = v << 16;
    unsigned hi = v & 0xFFFF0000u;
    u64 r; asm("mov.b64 %0, {%1, %2};" : "=l"(r) : "r"(lo), "r"(hi)); return r;
}

__device__ __forceinline__ float tanh_hw(float z) {
    float r; asm("tanh.approx.f32 %0, %1;" : "=f"(r) : "f"(z)); return r;
}
__device__ __forceinline__ float sig_hw(float z) {
    return __fmaf_rn(0.5f, tanh_hw(0.5f * z), 0.5f);
}
__device__ __forceinline__ float sig_exact(float z) {
    return __fdividef(1.0f, 1.0f + __expf(-z));
}
__device__ __forceinline__ float sel4(float v0, float v1, float v2, float v3, int ks) {
    float a = (ks & 1) ? v1 : v0;
    float b = (ks & 1) ? v3 : v2;
    return (ks & 2) ? b : a;
}

// write one bf16 weight into the lane-private stream layout w4[e4][512]
__device__ __forceinline__ void emit_w(char* wbase, int row, int z, int slice_len, float val) {
    int g = row >> 7, u = row & 127;
    int ks = z / slice_len, jr = z - ks * slice_len;
    int j = jr >> 2, pos = jr & 3;
    int t2 = u * 4 + ks;
    int e4 = j * 2 + (g >> 1);
    size_t byte = ((size_t)(e4 * 512 + t2)) * 16 + (((g & 1) << 1) | (pos >> 1)) * 4 + (pos & 1) * 2;
    *reinterpret_cast<__nv_bfloat16*>(wbase + byte) = __float2bfloat16(val);
}

// 32-FFMA2 inner chunk given weight uint4s already in registers
#define MM_BODY(wA, wB, zptr, jj)                                                  \
    {                                                                              \
        const float* zb = (zptr) + (jj) * 4;                                       \
        ulonglong2 z0 = *reinterpret_cast<const ulonglong2*>(zb);                  \
        ulonglong2 z1 = *reinterpret_cast<const ulonglong2*>(zb + ZLEN);           \
        ulonglong2 z2 = *reinterpret_cast<const ulonglong2*>(zb + 2 * ZLEN);       \
        ulonglong2 z3 = *reinterpret_cast<const ulonglong2*>(zb + 3 * ZLEN);       \
        u64 wg0a = bfpair((wA).x), wg0b = bfpair((wA).y);                          \
        u64 wg1a = bfpair((wA).z), wg1b = bfpair((wA).w);                          \
        u64 wg2a = bfpair((wB).x), wg2b = bfpair((wB).y);                          \
        u64 wg3a = bfpair((wB).z), wg3b = bfpair((wB).w);                          \
        fma2(acc[0][0], wg0a, z0.x); fma2(acc[0][0], wg0b, z0.y);                  \
        fma2(acc[0][1], wg0a, z1.x); fma2(acc[0][1], wg0b, z1.y);                  \
        fma2(acc[0][2], wg0a, z2.x); fma2(acc[0][2], wg0b, z2.y);                  \
        fma2(acc[0][3], wg0a, z3.x); fma2(acc[0][3], wg0b, z3.y);                  \
        fma2(acc[1][0], wg1a, z0.x); fma2(acc[1][0], wg1b, z0.y);                  \
        fma2(acc[1][1], wg1a, z1.x); fma2(acc[1][1], wg1b, z1.y);                  \
        fma2(acc[1][2], wg1a, z2.x); fma2(acc[1][2], wg1b, z2.y);                  \
        fma2(acc[1][3], wg1a, z3.x); fma2(acc[1][3], wg1b, z3.y);                  \
        fma2(acc[2][0], wg2a, z0.x); fma2(acc[2][0], wg2b, z0.y);                  \
        fma2(acc[2][1], wg2a, z1.x); fma2(acc[2][1], wg2b, z1.y);                  \
        fma2(acc[2][2], wg2a, z2.x); fma2(acc[2][2], wg2b, z2.y);                  \
        fma2(acc[2][3], wg2a, z3.x); fma2(acc[2][3], wg2b, z3.y);                  \
        fma2(acc[3][0], wg3a, z0.x); fma2(acc[3][0], wg3b, z0.y);                  \
        fma2(acc[3][1], wg3a, z1.x); fma2(acc[3][1], wg3b, z1.y);                  \
        fma2(acc[3][2], wg3a, z2.x); fma2(acc[3][2], wg3b, z2.y);                  \
        fma2(acc[3][3], wg3a, z3.x); fma2(acc[3][3], wg3b, z3.y);                  \
    }

// fold f32x2 lanes, butterfly over the 4 ks lanes
#define REDUCE_ACCS()                                                              \
    float gv[4][4];                                                                \
    _Pragma("unroll")                                                              \
    for (int gi = 0; gi < 4; ++gi)                                                 \
        _Pragma("unroll")                                                          \
        for (int bi = 0; bi < 4; ++bi) {                                           \
            float2 f = unpack2(acc[gi][bi]);                                       \
            float v = f.x + f.y;                                                   \
            v += __shfl_xor_sync(0xFFFFFFFFu, v, 1);                               \
            v += __shfl_xor_sync(0xFFFFFFFFu, v, 2);                               \
            gv[gi][bi] = v;                                                        \
        }

struct __align__(16) SmemL0 {
    uint4 w[W0_E4 * 512];           // staging; entries 16..19 stay resident for x-chunks
    float z[2][BT][ZLEN];
};
struct __align__(16) SmemL1 {
    uint4 w[W1_E4 * 512];           // staging only (drained into registers)
    float z[2][BT][ZLEN];
    float xp[2][BT][GG];
    float fcred[BT][2];
};

// ---------------- Layer 0: fused input proj + recurrence ----------------
__global__ void __launch_bounds__(512, 1)
lstm_layer0(const float* __restrict__ x, const float* __restrict__ Wih,
            const float* __restrict__ Whh, const float* __restrict__ bih,
            const float* __restrict__ bhh)
{
    extern __shared__ char smem_raw[];
    SmemL0& s = *reinterpret_cast<SmemL0*>(smem_raw);
    const int tid = threadIdx.x;
    const int bb  = blockIdx.x * BT;
    const int u   = tid >> 2, ks = tid & 3;

    // ---- init: zero weight staging + z, scatter-pack weights ----
    for (int i = tid; i < W0_E4 * 512; i += 512) s.w[i] = make_uint4(0, 0, 0, 0);
    for (int i = tid; i < 2 * BT * ZLEN; i += 512) (&s.z[0][0][0])[i] = 0.0f;
    __syncthreads();
    for (int i = tid; i < GG * HH; i += 512)
        emit_w((char*)s.w, i >> 7, i & 127, 40, Whh[i]);
    for (int i = tid; i < GG * KIN; i += 512) {
        int row = i / KIN, k = i - row * KIN;
        emit_w((char*)s.w, row, 128 + k, 40, Wih[i]);
    }
    float bias_g[4];
    #pragma unroll
    for (int gi = 0; gi < 4; ++gi)
        bias_g[gi] = bih[gi * 128 + u] + bhh[gi * 128 + u];
    const bool is_xthr = (tid < BT * KIN);
    const int  xb_ = is_xthr ? tid / KIN : 0;
    const int  xj  = is_xthr ? tid - (tid / KIN) * KIN : 0;
    if (is_xthr) s.z[0][xb_][128 + xj] = x[((size_t)(bb + xb_) * TT) * KIN + xj];
    __syncthreads();

    // ---- hoist chunks 0..7 weights into registers (loop-invariant) ----
    uint4 wreg[16];
    #pragma unroll
    for (int e = 0; e < 16; ++e) wreg[e] = s.w[e * 512 + tid];

    float c = 0.0f;
    const int wu = tid & 127, wb = tid >> 7;   // coalesced writeback mapping

    for (int t = 0; t < TT; ++t) {
        const int cur = t & 1, nxt = cur ^ 1;
        float xr = 0.0f;
        const bool pf = is_xthr && (t + 1 < TT);
        if (pf) xr = x[((size_t)(bb + xb_) * TT + (t + 1)) * KIN + xj];

        if (t > 0)
            g_h1[((size_t)(bb + wb) * TT + (t - 1)) * HH + wu] = s.z[cur][wb][wu];

        u64 acc[4][4];
        #pragma unroll
        for (int gi = 0; gi < 4; ++gi)
            #pragma unroll
            for (int bi = 0; bi < 4; ++bi) acc[gi][bi] = 0ull;

        const float* zbase = &s.z[cur][0][ks * 40];
        #pragma unroll
        for (int j = 0; j < 8; ++j)
            MM_BODY(wreg[j * 2], wreg[j * 2 + 1], zbase, j);
        #pragma unroll
        for (int j = 8; j < NJ0; ++j) {
            uint4 wA = s.w[(j * 2 + 0) * 512 + tid];
            uint4 wB = s.w[(j * 2 + 1) * 512 + tid];
            MM_BODY(wA, wB, zbase, j);
        }

        REDUCE_ACCS();

        float zi = sel4(gv[0][0], gv[0][1], gv[0][2], gv[0][3], ks) + bias_g[0];
        float zf = sel4(gv[1][0], gv[1][1], gv[1][2], gv[1][3], ks) + bias_g[1];
        float zg = sel4(gv[2][0], gv[2][1], gv[2][2], gv[2][3], ks) + bias_g[2];
        float zo = sel4(gv[3][0], gv[3][1], gv[3][2], gv[3][3], ks) + bias_g[3];
        float ig = sig_hw(zi), fg = sig_hw(zf), cg = tanh_hw(zg), og = sig_hw(zo);
        c = __fmaf_rn(fg, c, ig * cg);
        float hv = og * tanh_hw(c);

        s.z[nxt][ks][u] = hv;
        if (pf) s.z[nxt][xb_][128 + xj] = xr;
        __syncthreads();
    }
    g_h1[((size_t)(bb + wb) * TT + (TT - 1)) * HH + wu] = s.z[TT & 1][wb][wu];
}

// ------------- x_proj1 = h1 @ Wih1^T + bih1 + bhh1  (M=262144,N=512,K=128) -------------
#define AS_STRIDE 65
#define BS_STRIDE 68
__global__ void __launch_bounds__(256, 2)
xproj1_gemm(const float* __restrict__ Wih1, const float* __restrict__ bih1,
            const float* __restrict__ bhh1)
{
    extern __shared__ char smem_raw[];
    float* As = reinterpret_cast<float*>(smem_raw);  // [128][65]
    float* Bs = As + 128 * AS_STRIDE;                // [128][68]
    const int tid = threadIdx.x;
    const int tn = tid & 15, tm = tid >> 4;
    const int mBase = blockIdx.y * 64, nBase = blockIdx.x * 64;

    for (int e = tid; e < 64 * 128; e += 256) {
        int r = e >> 7, k = e & 127;
        As[k * AS_STRIDE + r] = g_h1[(size_t)(mBase + r) * HH + k];
        Bs[k * BS_STRIDE + r] = Wih1[(nBase + r) * HH + k];
    }
    __syncthreads();

    u64 acc[4][2];
    {
        const int n0 = nBase + tn * 4;
        u64 b01 = pack2(bih1[n0 + 0] + bhh1[n0 + 0], bih1[n0 + 1] + bhh1[n0 + 1]);
        u64 b23 = pack2(bih1[n0 + 2] + bhh1[n0 + 2], bih1[n0 + 3] + bhh1[n0 + 3]);
        #pragma unroll
        for (int i = 0; i < 4; ++i) { acc[i][0] = b01; acc[i][1] = b23; }
    }

    #pragma unroll 8
    for (int k = 0; k < 128; ++k) {
        const float* ar = &As[k * AS_STRIDE + tm * 4];
        u64 d0 = pack2(ar[0], ar[0]);
        u64 d1 = pack2(ar[1], ar[1]);
        u64 d2 = pack2(ar[2], ar[2]);
        u64 d3 = pack2(ar[3], ar[3]);
        ulonglong2 bv = *reinterpret_cast<const ulonglong2*>(&Bs[k * BS_STRIDE + tn * 4]);
        fma2(acc[0][0], d0, bv.x); fma2(acc[0][1], d0, bv.y);
        fma2(acc[1][0], d1, bv.x); fma2(acc[1][1], d1, bv.y);
        fma2(acc[2][0], d2, bv.x); fma2(acc[2][1], d2, bv.y);
        fma2(acc[3][0], d3, bv.x); fma2(acc[3][1], d3, bv.y);
    }

    #pragma unroll
    for (int i = 0; i < 4; ++i) {
        size_t m = (size_t)(mBase + tm * 4 + i);
        ulonglong2 o; o.x = acc[i][0]; o.y = acc[i][1];
        *reinterpret_cast<ulonglong2*>(&g_xp1[m * GG + nBase + tn * 4]) = o;
    }
}

// ------- Layer 1 recurrence (xp1 + h @ Whh1^T), FC head fused at the end -------
__global__ void __launch_bounds__(512, 1)
lstm_layer1(const float* __restrict__ Whh,
            const float* __restrict__ Wfc1, const float* __restrict__ bfc1,
            const float* __restrict__ Wfc2, const float* __restrict__ bfc2,
            float* __restrict__ out)
{
    extern __shared__ char smem_raw[];
    SmemL1& s = *reinterpret_cast<SmemL1*>(smem_raw);
    const int tid = threadIdx.x;
    const int bb  = blockIdx.x * BT;
    const int u   = tid >> 2, ks = tid & 3;

    for (int i = tid; i < 2 * BT * ZLEN; i += 512) (&s.z[0][0][0])[i] = 0.0f;
    __syncthreads();
    for (int i = tid; i < GG * HH; i += 512)
        emit_w((char*)s.w, i >> 7, i & 127, 32, Whh[i]);
    const int xb = tid >> 7, xr4 = (tid & 127) * 4;
    {
        float4 v = *reinterpret_cast<const float4*>(
            &g_xp1[((size_t)(bb + xb) * TT + 0) * GG + xr4]);
        *reinterpret_cast<float4*>(&s.xp[0][xb][xr4]) = v;
    }
    __syncthreads();

    // ---- hoist all weights into registers ----
    uint4 wreg[16];
    #pragma unroll
    for (int e = 0; e < 16; ++e) wreg[e] = s.w[e * 512 + tid];

    float c = 0.0f;

    for (int t = 0; t < TT; ++t) {
        const int cur = t & 1, nxt = cur ^ 1;
        float4 xpn = make_float4(0.f, 0.f, 0.f, 0.f);
        const bool pf = (t + 1 < TT);
        if (pf) xpn = *reinterpret_cast<const float4*>(
            &g_xp1[((size_t)(bb + xb) * TT + (t + 1)) * GG + xr4]);

        u64 acc[4][4];
        #pragma unroll
        for (int gi = 0; gi < 4; ++gi)
            #pragma unroll
            for (int bi = 0; bi < 4; ++bi) acc[gi][bi] = 0ull;

        const float* zbase = &s.z[cur][0][ks * 40];
        #pragma unroll
        for (int j = 0; j < NJ1; ++j)
            MM_BODY(wreg[j * 2], wreg[j * 2 + 1], zbase, j);

        if (pf) *reinterpret_cast<float4*>(&s.xp[nxt][xb][xr4]) = xpn;

        REDUCE_ACCS();

        const float* xpc = &s.xp[cur][ks][0];
        float zi = sel4(gv[0][0], gv[0][1], gv[0][2], gv[0][3], ks) + xpc[      u];
        float zf = sel4(gv[1][0], gv[1][1], gv[1][2], gv[1][3], ks) + xpc[128 + u];
        float zg = sel4(gv[2][0], gv[2][1], gv[2][2], gv[2][3], ks) + xpc[256 + u];
        float zo = sel4(gv[3][0], gv[3][1], gv[3][2], gv[3][3], ks) + xpc[384 + u];
        float ig = sig_hw(zi), fg = sig_hw(zf), cg = tanh_hw(zg), og = sig_hw(zo);
        c = __fmaf_rn(fg, c, ig * cg);
        float hv = og * tanh_hw(c);

        s.z[nxt][ks][(u >> 5) * 40 + (u & 31)] = hv;   // padded slice layout
        __syncthreads();
    }

    // ---- fused FC head on final h (exact math) ----
    const int fin = TT & 1;
    if (tid < 256) {
        const int bl = tid >> 6, j = tid & 63;
        float accf = bfc1[j];
        const float* wr = &Wfc1[j * HH];
        #pragma unroll 8
        for (int k = 0; k < HH; ++k)
            accf = __fmaf_rn(s.z[fin][bl][(k >> 5) * 40 + (k & 31)], wr[k], accf);
        float v = fmaxf(accf, 0.0f) * Wfc2[j];
        #pragma unroll
        for (int off = 16; off > 0; off >>= 1)
            v += __shfl_down_sync(0xFFFFFFFFu, v, off);
        if ((j & 31) == 0) s.fcred[bl][j >> 5] = v;
    }
    __syncthreads();
    if (tid < BT) {
        float z = s.fcred[tid][0] + s.fcred[tid][1] + bfc2[0];
        out[bb + tid] = sig_exact(z);
    }
}

extern "C" void kernel_launch(void* const* d_in, const int* in_sizes, int n_in,
                              void* d_out, int out_size)
{
    const float* x     = (const float*)d_in[0];
    const float* Wih0  = (const float*)d_in[1];
    const float* Whh0  = (const float*)d_in[2];
    const float* bih0  = (const float*)d_in[3];
    const float* bhh0  = (const float*)d_in[4];
    const float* Wih1  = (const float*)d_in[5];
    const float* Whh1  = (const float*)d_in[6];
    const float* bih1  = (const float*)d_in[7];
    const float* bhh1  = (const float*)d_in[8];
    const float* Wfc1  = (const float*)d_in[9];
    const float* bfc1  = (const float*)d_in[10];
    const float* Wfc2  = (const float*)d_in[11];
    const float* bfc2  = (const float*)d_in[12];
    float* out = (float*)d_out;

    static bool attr_done = false;
    if (!attr_done) {
        cudaFuncSetAttribute(lstm_layer0, cudaFuncAttributeMaxDynamicSharedMemorySize,
                             (int)sizeof(SmemL0));
        cudaFuncSetAttribute(lstm_layer1, cudaFuncAttributeMaxDynamicSharedMemorySize,
                             (int)sizeof(SmemL1));
        cudaFuncSetAttribute(xproj1_gemm, cudaFuncAttributeMaxDynamicSharedMemorySize,
                             (128 * AS_STRIDE + 128 * BS_STRIDE) * (int)sizeof(float));
        attr_done = true;
    }

    lstm_layer0<<<NBLK, 512, sizeof(SmemL0)>>>(x, Wih0, Whh0, bih0, bhh0);
    {
        dim3 grid(GG / 64, (BB * TT) / 64);
        xproj1_gemm<<<grid, 256, (128 * AS_STRIDE + 128 * BS_STRIDE) * sizeof(float)>>>(
            Wih1, bih1, bhh1);
    }
    lstm_layer1<<<NBLK, 512, sizeof(SmemL1)>>>(Whh1, Wfc1, bfc1, Wfc2, bfc2, out);
}

// round 15
// speedup vs baseline: 1.9207x; 1.9207x over previous
#include <cuda_runtime.h>
#include <cuda_bf16.h>
#include <cstdint>

#define HH   128
#define GG   512          // 4*H
#define TT   512
#define BB   512
#define KIN  18
#define BT   4            // batches per CTA
#define NBLK (BB / BT)

#define ZLEN   160        // z stride per batch
#define NJ0    10         // j-chunks per slice, layer0 (40 k's)
#define NJ1    8          // j-chunks per slice, layer1 (32 k's)
#define W0_E4  (NJ0 * 2)
#define W1_E4  (NJ1 * 2)

typedef unsigned long long u64;

// static scratch (no allocation allowed in kernel_launch)
__device__ float g_h1[(size_t)BB * TT * HH];     // layer0 hidden
__device__ float g_xp1[(size_t)BB * TT * GG];    // layer1 input proj

// ---- packed fp32x2 helpers (SASS FFMA2; only reachable via PTX) ----
__device__ __forceinline__ u64 pack2(float lo, float hi) {
    u64 r; asm("mov.b64 %0, {%1, %2};" : "=l"(r) : "f"(lo), "f"(hi)); return r;
}
__device__ __forceinline__ float2 unpack2(u64 v) {
    float2 r; asm("mov.b64 {%0, %1}, %2;" : "=f"(r.x), "=f"(r.y) : "l"(v)); return r;
}
__device__ __forceinline__ void fma2(u64& d, u64 a, u64 b) {
    asm("fma.rn.f32x2 %0, %1, %2, %0;" : "+l"(d) : "l"(a), "l"(b));
}
__device__ __forceinline__ u64 bfpair(unsigned v) {
    unsigned lo = v << 16;
    unsigned hi = v & 0xFFFF0000u;
    u64 r; asm("mov.b64 %0, {%1, %2};" : "=l"(r) : "r"(lo), "r"(hi)); return r;
}

__device__ __forceinline__ float tanh_hw(float z) {
    float r; asm("tanh.approx.f32 %0, %1;" : "=f"(r) : "f"(z)); return r;
}
__device__ __forceinline__ float sig_hw(float z) {
    return __fmaf_rn(0.5f, tanh_hw(0.5f * z), 0.5f);
}
__device__ __forceinline__ float sig_exact(float z) {
    return __fdividef(1.0f, 1.0f + __expf(-z));
}
__device__ __forceinline__ float sel4(float v0, float v1, float v2, float v3, int ks) {
    float a = (ks & 1) ? v1 : v0;
    float b = (ks & 1) ? v3 : v2;
    return (ks & 2) ? b : a;
}

// write one bf16 weight into the lane-private stream layout w4[e4][512]
__device__ __forceinline__ void emit_w(char* wbase, int row, int z, int slice_len, float val) {
    int g = row >> 7, u = row & 127;
    int ks = z / slice_len, jr = z - ks * slice_len;
    int j = jr >> 2, pos = jr & 3;
    int t2 = u * 4 + ks;
    int e4 = j * 2 + (g >> 1);
    size_t byte = ((size_t)(e4 * 512 + t2)) * 16 + (((g & 1) << 1) | (pos >> 1)) * 4 + (pos & 1) * 2;
    *reinterpret_cast<__nv_bfloat16*>(wbase + byte) = __float2bfloat16(val);
}

// 32-FFMA2 inner chunk (weights streamed from SMEM — R10 proven layout)
#define MM_CHUNK(wptr, zptr, jj)                                                   \
    {                                                                              \
        uint4 wA = (wptr)[((jj) * 2 + 0) * 512 + tid];                             \
        uint4 wB = (wptr)[((jj) * 2 + 1) * 512 + tid];                             \
        const float* zb = (zptr) + (jj) * 4;                                       \
        ulonglong2 z0 = *reinterpret_cast<const ulonglong2*>(zb);                  \
        ulonglong2 z1 = *reinterpret_cast<const ulonglong2*>(zb + ZLEN);           \
        ulonglong2 z2 = *reinterpret_cast<const ulonglong2*>(zb + 2 * ZLEN);       \
        ulonglong2 z3 = *reinterpret_cast<const ulonglong2*>(zb + 3 * ZLEN);       \
        u64 wg0a = bfpair(wA.x), wg0b = bfpair(wA.y);                              \
        u64 wg1a = bfpair(wA.z), wg1b = bfpair(wA.w);                              \
        u64 wg2a = bfpair(wB.x), wg2b = bfpair(wB.y);                              \
        u64 wg3a = bfpair(wB.z), wg3b = bfpair(wB.w);                              \
        fma2(acc[0][0], wg0a, z0.x); fma2(acc[0][0], wg0b, z0.y);                  \
        fma2(acc[0][1], wg0a, z1.x); fma2(acc[0][1], wg0b, z1.y);                  \
        fma2(acc[0][2], wg0a, z2.x); fma2(acc[0][2], wg0b, z2.y);                  \
        fma2(acc[0][3], wg0a, z3.x); fma2(acc[0][3], wg0b, z3.y);                  \
        fma2(acc[1][0], wg1a, z0.x); fma2(acc[1][0], wg1b, z0.y);                  \
        fma2(acc[1][1], wg1a, z1.x); fma2(acc[1][1], wg1b, z1.y);                  \
        fma2(acc[1][2], wg1a, z2.x); fma2(acc[1][2], wg1b, z2.y);                  \
        fma2(acc[1][3], wg1a, z3.x); fma2(acc[1][3], wg1b, z3.y);                  \
        fma2(acc[2][0], wg2a, z0.x); fma2(acc[2][0], wg2b, z0.y);                  \
        fma2(acc[2][1], wg2a, z1.x); fma2(acc[2][1], wg2b, z1.y);                  \
        fma2(acc[2][2], wg2a, z2.x); fma2(acc[2][2], wg2b, z2.y);                  \
        fma2(acc[2][3], wg2a, z3.x); fma2(acc[2][3], wg2b, z3.y);                  \
        fma2(acc[3][0], wg3a, z0.x); fma2(acc[3][0], wg3b, z0.y);                  \
        fma2(acc[3][1], wg3a, z1.x); fma2(acc[3][1], wg3b, z1.y);                  \
        fma2(acc[3][2], wg3a, z2.x); fma2(acc[3][2], wg3b, z2.y);                  \
        fma2(acc[3][3], wg3a, z3.x); fma2(acc[3][3], wg3b, z3.y);                  \
    }

#define REDUCE_ACCS()                                                              \
    float gv[4][4];                                                                \
    _Pragma("unroll")                                                              \
    for (int gi = 0; gi < 4; ++gi)                                                 \
        _Pragma("unroll")                                                          \
        for (int bi = 0; bi < 4; ++bi) {                                           \
            float2 f = unpack2(acc[gi][bi]);                                       \
            float v = f.x + f.y;                                                   \
            v += __shfl_xor_sync(0xFFFFFFFFu, v, 1);                               \
            v += __shfl_xor_sync(0xFFFFFFFFu, v, 2);                               \
            gv[gi][bi] = v;                                                        \
        }

struct __align__(16) SmemL0 {
    uint4 w[W0_E4 * 512];
    float z[2][BT][ZLEN];
};
struct __align__(16) SmemL1 {
    uint4 w[W1_E4 * 512];
    float z[2][BT][ZLEN];
    float xp[2][BT][GG];
    float fcred[BT][2];
};

// ---------------- Layer 0: fused input proj + recurrence (R10 proven) ----------------
__global__ void __launch_bounds__(512, 1)
lstm_layer0(const float* __restrict__ x, const float* __restrict__ Wih,
            const float* __restrict__ Whh, const float* __restrict__ bih,
            const float* __restrict__ bhh)
{
    extern __shared__ char smem_raw[];
    SmemL0& s = *reinterpret_cast<SmemL0*>(smem_raw);
    const int tid = threadIdx.x;
    const int bb  = blockIdx.x * BT;
    const int u   = tid >> 2, ks = tid & 3;

    for (int i = tid; i < W0_E4 * 512; i += 512) s.w[i] = make_uint4(0, 0, 0, 0);
    for (int i = tid; i < 2 * BT * ZLEN; i += 512) (&s.z[0][0][0])[i] = 0.0f;
    __syncthreads();
    for (int i = tid; i < GG * HH; i += 512)
        emit_w((char*)s.w, i >> 7, i & 127, 40, Whh[i]);
    for (int i = tid; i < GG * KIN; i += 512) {
        int row = i / KIN, k = i - row * KIN;
        emit_w((char*)s.w, row, 128 + k, 40, Wih[i]);
    }
    float bias_g[4];
    #pragma unroll
    for (int gi = 0; gi < 4; ++gi)
        bias_g[gi] = bih[gi * 128 + u] + bhh[gi * 128 + u];
    const bool is_xthr = (tid < BT * KIN);
    const int  xb_ = is_xthr ? tid / KIN : 0;
    const int  xj  = is_xthr ? tid - (tid / KIN) * KIN : 0;
    if (is_xthr) s.z[0][xb_][128 + xj] = x[((size_t)(bb + xb_) * TT) * KIN + xj];
    __syncthreads();

    float c = 0.0f;
    const int wu = tid & 127, wb = tid >> 7;

    for (int t = 0; t < TT; ++t) {
        const int cur = t & 1, nxt = cur ^ 1;
        float xr = 0.0f;
        const bool pf = is_xthr && (t + 1 < TT);
        if (pf) xr = x[((size_t)(bb + xb_) * TT + (t + 1)) * KIN + xj];

        if (t > 0)
            g_h1[((size_t)(bb + wb) * TT + (t - 1)) * HH + wu] = s.z[cur][wb][wu];

        u64 acc[4][4];
        #pragma unroll
        for (int gi = 0; gi < 4; ++gi)
            #pragma unroll
            for (int bi = 0; bi < 4; ++bi) acc[gi][bi] = 0ull;

        const float* zbase = &s.z[cur][0][ks * 40];
        #pragma unroll
        for (int j = 0; j < NJ0; ++j) MM_CHUNK(s.w, zbase, j);

        REDUCE_ACCS();

        float zi = sel4(gv[0][0], gv[0][1], gv[0][2], gv[0][3], ks) + bias_g[0];
        float zf = sel4(gv[1][0], gv[1][1], gv[1][2], gv[1][3], ks) + bias_g[1];
        float zg = sel4(gv[2][0], gv[2][1], gv[2][2], gv[2][3], ks) + bias_g[2];
        float zo = sel4(gv[3][0], gv[3][1], gv[3][2], gv[3][3], ks) + bias_g[3];
        float ig = sig_hw(zi), fg = sig_hw(zf), cg = tanh_hw(zg), og = sig_hw(zo);
        c = __fmaf_rn(fg, c, ig * cg);
        float hv = og * tanh_hw(c);

        s.z[nxt][ks][u] = hv;
        if (pf) s.z[nxt][xb_][128 + xj] = xr;
        __syncthreads();
    }
    g_h1[((size_t)(bb + wb) * TT + (TT - 1)) * HH + wu] = s.z[TT & 1][wb][wu];
}

// ===== x_proj1 via warp-level mma.sync (bf16, sm_80+ PTX — legal on compute_103) =====
// Persistent CTAs; per tile: M=128, N=512, K=128. 8 warps x (M=16 stripe).
#define GT_TILES ((BB * TT) / 128)    // 2048
#define XP_THREADS 256
#define AST 68                        // A row stride in b32 words (64 data + 4 pad)
#define BST 68                        // B row stride in b32 words
#define XP_BIAS_OFF 0                 // 512 f32 = 2048 B
#define XP_A_OFF    2048              // 128*68*4 = 34816 B
#define XP_B_OFF    (2048 + 34816)    // 512*68*4 = 139264 B
#define XP_SMEM     (XP_B_OFF + 139264)

__device__ __forceinline__ unsigned cvt_bf2(float lo, float hi) {
    unsigned r; asm("cvt.rn.bf16x2.f32 %0, %1, %2;" : "=r"(r) : "f"(hi), "f"(lo)); return r;
}
__device__ __forceinline__ void mma16816(float* d, unsigned a0, unsigned a1,
                                         unsigned a2, unsigned a3,
                                         unsigned b0, unsigned b1) {
    asm("mma.sync.aligned.m16n8k16.row.col.f32.bf16.bf16.f32 "
        "{%0,%1,%2,%3}, {%4,%5,%6,%7}, {%8,%9}, {%0,%1,%2,%3};"
        : "+f"(d[0]), "+f"(d[1]), "+f"(d[2]), "+f"(d[3])
        : "r"(a0), "r"(a1), "r"(a2), "r"(a3), "r"(b0), "r"(b1));
}

__global__ void __launch_bounds__(XP_THREADS, 1)
xproj1_mma(const float* __restrict__ Wih1, const float* __restrict__ bih1,
           const float* __restrict__ bhh1)
{
    extern __shared__ char smem[];
    float*    bias = reinterpret_cast<float*>(smem + XP_BIAS_OFF);
    unsigned* As   = reinterpret_cast<unsigned*>(smem + XP_A_OFF);  // [m][kword]
    unsigned* Bs   = reinterpret_cast<unsigned*>(smem + XP_B_OFF);  // [n][kword]
    const int tid  = threadIdx.x;
    const int wid  = tid >> 5, lane = tid & 31;
    const int l4   = lane >> 2, l2 = lane & 3;

    for (int i = tid; i < GG; i += XP_THREADS) bias[i] = bih1[i] + bhh1[i];
    for (int i = tid; i < GG * 64; i += XP_THREADS) {      // i = n*64 + kword
        int n = i >> 6, kw = i & 63;
        float2 v = *reinterpret_cast<const float2*>(&Wih1[(size_t)n * HH + kw * 2]);
        Bs[n * BST + kw] = cvt_bf2(v.x, v.y);
    }
    __syncthreads();

    for (int tile = blockIdx.x; tile < GT_TILES; tile += gridDim.x) {
        const size_t mBase = (size_t)tile * 128;

        // A tile f32 -> bf16x2 words
        for (int i = tid; i < 128 * 64; i += XP_THREADS) { // i = m*64 + kword
            int m = i >> 6, kw = i & 63;
            float2 v = *reinterpret_cast<const float2*>(&g_h1[(mBase + m) * HH + kw * 2]);
            As[m * AST + kw] = cvt_bf2(v.x, v.y);
        }
        __syncthreads();

        const int r0 = wid * 16 + l4;                      // this lane's D row (and +8)
        const unsigned* Ar0 = As + r0 * AST;
        const unsigned* Ar1 = As + (r0 + 8) * AST;
        const size_t gm0 = (mBase + r0) * GG;
        const size_t gm1 = (mBase + r0 + 8) * GG;

        #pragma unroll 1
        for (int nc = 0; nc < 8; ++nc) {                   // n-chunks of 64
            float acc[8][4];
            #pragma unroll
            for (int nt = 0; nt < 8; ++nt)
                #pragma unroll
                for (int q = 0; q < 4; ++q) acc[nt][q] = 0.0f;

            #pragma unroll
            for (int ks = 0; ks < 8; ++ks) {               // k-steps of 16
                const int kb = ks * 8 + l2;
                unsigned a0 = Ar0[kb], a1 = Ar1[kb];
                unsigned a2 = Ar0[kb + 4], a3 = Ar1[kb + 4];
                #pragma unroll
                for (int nt = 0; nt < 8; ++nt) {
                    const unsigned* Bn = Bs + (nc * 64 + nt * 8 + l4) * BST;
                    mma16816(acc[nt], a0, a1, a2, a3, Bn[kb], Bn[kb + 4]);
                }
            }

            #pragma unroll
            for (int nt = 0; nt < 8; ++nt) {
                const int nb = nc * 64 + nt * 8 + l2 * 2;
                float b0 = bias[nb], b1 = bias[nb + 1];
                float2 lo = make_float2(acc[nt][0] + b0, acc[nt][1] + b1);
                float2 hi = make_float2(acc[nt][2] + b0, acc[nt][3] + b1);
                *reinterpret_cast<float2*>(&g_xp1[gm0 + nb]) = lo;
                *reinterpret_cast<float2*>(&g_xp1[gm1 + nb]) = hi;
            }
        }
        __syncthreads();   // all warps done reading As before next tile overwrites it
    }
}

// ------- Layer 1 recurrence (xp1 + h @ Whh1^T), FC head fused (R10 proven) -------
__global__ void __launch_bounds__(512, 1)
lstm_layer1(const float* __restrict__ Whh,
            const float* __restrict__ Wfc1, const float* __restrict__ bfc1,
            const float* __restrict__ Wfc2, const float* __restrict__ bfc2,
            float* __restrict__ out)
{
    extern __shared__ char smem_raw[];
    SmemL1& s = *reinterpret_cast<SmemL1*>(smem_raw);
    const int tid = threadIdx.x;
    const int bb  = blockIdx.x * BT;
    const int u   = tid >> 2, ks = tid & 3;

    for (int i = tid; i < W1_E4 * 512; i += 512) s.w[i] = make_uint4(0, 0, 0, 0);
    for (int i = tid; i < 2 * BT * ZLEN; i += 512) (&s.z[0][0][0])[i] = 0.0f;
    __syncthreads();
    for (int i = tid; i < GG * HH; i += 512)
        emit_w((char*)s.w, i >> 7, i & 127, 32, Whh[i]);
    const int xb = tid >> 7, xr4 = (tid & 127) * 4;
    {
        float4 v = *reinterpret_cast<const float4*>(
            &g_xp1[((size_t)(bb + xb) * TT + 0) * GG + xr4]);
        *reinterpret_cast<float4*>(&s.xp[0][xb][xr4]) = v;
    }
    __syncthreads();

    float c = 0.0f;

    for (int t = 0; t < TT; ++t) {
        const int cur = t & 1, nxt = cur ^ 1;
        float4 xpn = make_float4(0.f, 0.f, 0.f, 0.f);
        const bool pf = (t + 1 < TT);
        if (pf) xpn = *reinterpret_cast<const float4*>(
            &g_xp1[((size_t)(bb + xb) * TT + (t + 1)) * GG + xr4]);

        u64 acc[4][4];
        #pragma unroll
        for (int gi = 0; gi < 4; ++gi)
            #pragma unroll
            for (int bi = 0; bi < 4; ++bi) acc[gi][bi] = 0ull;

        const float* zbase = &s.z[cur][0][ks * 40];
        #pragma unroll
        for (int j = 0; j < NJ1; ++j) MM_CHUNK(s.w, zbase, j);

        if (pf) *reinterpret_cast<float4*>(&s.xp[nxt][xb][xr4]) = xpn;

        REDUCE_ACCS();

        const float* xpc = &s.xp[cur][ks][0];
        float zi = sel4(gv[0][0], gv[0][1], gv[0][2], gv[0][3], ks) + xpc[      u];
        float zf = sel4(gv[1][0], gv[1][1], gv[1][2], gv[1][3], ks) + xpc[128 + u];
        float zg = sel4(gv[2][0], gv[2][1], gv[2][2], gv[2][3], ks) + xpc[256 + u];
        float zo = sel4(gv[3][0], gv[3][1], gv[3][2], gv[3][3], ks) + xpc[384 + u];
        float ig = sig_hw(zi), fg = sig_hw(zf), cg = tanh_hw(zg), og = sig_hw(zo);
        c = __fmaf_rn(fg, c, ig * cg);
        float hv = og * tanh_hw(c);

        s.z[nxt][ks][(u >> 5) * 40 + (u & 31)] = hv;
        __syncthreads();
    }

    const int fin = TT & 1;
    if (tid < 256) {
        const int bl = tid >> 6, j = tid & 63;
        float accf = bfc1[j];
        const float* wr = &Wfc1[j * HH];
        #pragma unroll 8
        for (int k = 0; k < HH; ++k)
            accf = __fmaf_rn(s.z[fin][bl][(k >> 5) * 40 + (k & 31)], wr[k], accf);
        float v = fmaxf(accf, 0.0f) * Wfc2[j];
        #pragma unroll
        for (int off = 16; off > 0; off >>= 1)
            v += __shfl_down_sync(0xFFFFFFFFu, v, off);
        if ((j & 31) == 0) s.fcred[bl][j >> 5] = v;
    }
    __syncthreads();
    if (tid < BT) {
        float z = s.fcred[tid][0] + s.fcred[tid][1] + bfc2[0];
        out[bb + tid] = sig_exact(z);
    }
}

extern "C" void kernel_launch(void* const* d_in, const int* in_sizes, int n_in,
                              void* d_out, int out_size)
{
    const float* x     = (const float*)d_in[0];
    const float* Wih0  = (const float*)d_in[1];
    const float* Whh0  = (const float*)d_in[2];
    const float* bih0  = (const float*)d_in[3];
    const float* bhh0  = (const float*)d_in[4];
    const float* Wih1  = (const float*)d_in[5];
    const float* Whh1  = (const float*)d_in[6];
    const float* bih1  = (const float*)d_in[7];
    const float* bhh1  = (const float*)d_in[8];
    const float* Wfc1  = (const float*)d_in[9];
    const float* bfc1  = (const float*)d_in[10];
    const float* Wfc2  = (const float*)d_in[11];
    const float* bfc2  = (const float*)d_in[12];
    float* out = (float*)d_out;

    static bool attr_done = false;
    if (!attr_done) {
        cudaFuncSetAttribute(lstm_layer0, cudaFuncAttributeMaxDynamicSharedMemorySize,
                             (int)sizeof(SmemL0));
        cudaFuncSetAttribute(lstm_layer1, cudaFuncAttributeMaxDynamicSharedMemorySize,
                             (int)sizeof(SmemL1));
        cudaFuncSetAttribute(xproj1_mma, cudaFuncAttributeMaxDynamicSharedMemorySize,
                             XP_SMEM);
        attr_done = true;
    }

    lstm_layer0<<<NBLK, 512, sizeof(SmemL0)>>>(x, Wih0, Whh0, bih0, bhh0);
    xproj1_mma<<<148, XP_THREADS, XP_SMEM>>>(Wih1, bih1, bhh1);
    lstm_layer1<<<NBLK, 512, sizeof(SmemL1)>>>(Whh1, Wfc1, bfc1, Wfc2, bfc2, out);
}

// round 16
// speedup vs baseline: 2.1534x; 1.1211x over previous
#include <cuda_runtime.h>
#include <cuda_bf16.h>
#include <cstdint>

#define HH   128
#define GG   512          // 4*H
#define TT   512
#define BB   512
#define KIN  18

typedef unsigned long long u64;

// static scratch (no allocation allowed in kernel_launch)
__device__ float g_h1[(size_t)BB * TT * HH];     // layer0 hidden (f32)
__device__ float g_xp0[(size_t)BB * TT * GG];    // layer0 input proj
__device__ float g_xp1[(size_t)BB * TT * GG];    // layer1 input proj

// ---- helpers ----
__device__ __forceinline__ float tanh_hw(float z) {
    float r; asm("tanh.approx.f32 %0, %1;" : "=f"(r) : "f"(z)); return r;
}
__device__ __forceinline__ float sig_hw(float z) {
    return __fmaf_rn(0.5f, tanh_hw(0.5f * z), 0.5f);
}
__device__ __forceinline__ float sig_exact(float z) {
    return __fdividef(1.0f, 1.0f + __expf(-z));
}
__device__ __forceinline__ unsigned cvt_bf2(float lo, float hi) {
    unsigned r; asm("cvt.rn.bf16x2.f32 %0, %1, %2;" : "=r"(r) : "f"(hi), "f"(lo)); return r;
}
// m16n8k16 row.col bf16 mma — fragment mapping empirically verified in R15
__device__ __forceinline__ void mma16816(float* d, unsigned a0, unsigned a1,
                                         unsigned a2, unsigned a3,
                                         unsigned b0, unsigned b1) {
    asm("mma.sync.aligned.m16n8k16.row.col.f32.bf16.bf16.f32 "
        "{%0,%1,%2,%3}, {%4,%5,%6,%7}, {%8,%9}, {%0,%1,%2,%3};"
        : "+f"(d[0]), "+f"(d[1]), "+f"(d[2]), "+f"(d[3])
        : "r"(a0), "r"(a1), "r"(a2), "r"(a3), "r"(b0), "r"(b1));
}

// ================= xp0 = x @ Wih0^T + bih0 + bhh0  (K=18 pad->32) =================
#define X0_TILES ((BB * TT) / 128)
#define X0_BIAS 0
#define X0_A    2048                 // 128 rows * 20 words * 4 B = 10240
#define X0_B    12288                // 512 rows * 20 words * 4 B = 40960
#define X0_SMEM 53248

__global__ void __launch_bounds__(256, 1)
xproj0_mma(const float* __restrict__ x, const float* __restrict__ Wih0,
           const float* __restrict__ bih0, const float* __restrict__ bhh0)
{
    extern __shared__ char smem[];
    float*    bias = reinterpret_cast<float*>(smem + X0_BIAS);
    unsigned* Aw   = reinterpret_cast<unsigned*>(smem + X0_A);   // [128][20]
    unsigned* Bw   = reinterpret_cast<unsigned*>(smem + X0_B);   // [512][20]
    const int tid = threadIdx.x;
    const int wid = tid >> 5, lane = tid & 31;
    const int l4  = lane >> 2, l2 = lane & 3;

    for (int i = tid; i < GG; i += 256) bias[i] = bih0[i] + bhh0[i];
    // zero pad words 9..19 (never rewritten)
    for (int i = tid; i < 128 * 11; i += 256) { int m = i / 11; Aw[m * 20 + 9 + i % 11] = 0u; }
    for (int i = tid; i < 512 * 11; i += 256) { int n = i / 11; Bw[n * 20 + 9 + i % 11] = 0u; }
    // B data words 0..8 (K=18 -> 9 bf16x2)
    for (int i = tid; i < 512 * 9; i += 256) {
        int n = i / 9, kp = i - n * 9;
        float2 v = *reinterpret_cast<const float2*>(&Wih0[n * KIN + kp * 2]);
        Bw[n * 20 + kp] = cvt_bf2(v.x, v.y);
    }
    __syncthreads();

    for (int tile = blockIdx.x; tile < X0_TILES; tile += gridDim.x) {
        const size_t mBase = (size_t)tile * 128;
        for (int i = tid; i < 128 * 9; i += 256) {
            int m = i / 9, kp = i - m * 9;
            float2 v = *reinterpret_cast<const float2*>(&x[(mBase + m) * KIN + kp * 2]);
            Aw[m * 20 + kp] = cvt_bf2(v.x, v.y);
        }
        __syncthreads();

        const int r0 = wid * 16 + l4;
        const unsigned* Ar0 = Aw + r0 * 20;
        const unsigned* Ar1 = Aw + (r0 + 8) * 20;
        const size_t gm0 = (mBase + r0) * GG;
        const size_t gm1 = (mBase + r0 + 8) * GG;

        #pragma unroll 1
        for (int nc = 0; nc < 8; ++nc) {
            float acc[8][4];
            #pragma unroll
            for (int nt = 0; nt < 8; ++nt)
                #pragma unroll
                for (int q = 0; q < 4; ++q) acc[nt][q] = 0.0f;

            #pragma unroll
            for (int ks = 0; ks < 2; ++ks) {
                const int kb = ks * 8 + l2;
                unsigned a0 = Ar0[kb], a1 = Ar1[kb];
                unsigned a2 = Ar0[kb + 4], a3 = Ar1[kb + 4];
                #pragma unroll
                for (int nt = 0; nt < 8; ++nt) {
                    const unsigned* Bn = Bw + (nc * 64 + nt * 8 + l4) * 20;
                    mma16816(acc[nt], a0, a1, a2, a3, Bn[kb], Bn[kb + 4]);
                }
            }
            #pragma unroll
            for (int nt = 0; nt < 8; ++nt) {
                const int nb = nc * 64 + nt * 8 + l2 * 2;
                float b0 = bias[nb], b1 = bias[nb + 1];
                *reinterpret_cast<float2*>(&g_xp0[gm0 + nb]) =
                    make_float2(acc[nt][0] + b0, acc[nt][1] + b1);
                *reinterpret_cast<float2*>(&g_xp0[gm1 + nb]) =
                    make_float2(acc[nt][2] + b0, acc[nt][3] + b1);
            }
        }
        __syncthreads();
    }
}

// ===== xp1 = h1 @ Wih1^T + bih1 + bhh1  (M=262144,N=512,K=128) — R15 proven =====
#define GT_TILES ((BB * TT) / 128)
#define XP_THREADS 256
#define AST 68
#define BST 68
#define XP_BIAS_OFF 0
#define XP_A_OFF    2048
#define XP_B_OFF    (2048 + 34816)
#define XP_SMEM     (XP_B_OFF + 139264)

__global__ void __launch_bounds__(XP_THREADS, 1)
xproj1_mma(const float* __restrict__ Wih1, const float* __restrict__ bih1,
           const float* __restrict__ bhh1)
{
    extern __shared__ char smem[];
    float*    bias = reinterpret_cast<float*>(smem + XP_BIAS_OFF);
    unsigned* As   = reinterpret_cast<unsigned*>(smem + XP_A_OFF);
    unsigned* Bs   = reinterpret_cast<unsigned*>(smem + XP_B_OFF);
    const int tid  = threadIdx.x;
    const int wid  = tid >> 5, lane = tid & 31;
    const int l4   = lane >> 2, l2 = lane & 3;

    for (int i = tid; i < GG; i += XP_THREADS) bias[i] = bih1[i] + bhh1[i];
    for (int i = tid; i < GG * 64; i += XP_THREADS) {
        int n = i >> 6, kw = i & 63;
        float2 v = *reinterpret_cast<const float2*>(&Wih1[(size_t)n * HH + kw * 2]);
        Bs[n * BST + kw] = cvt_bf2(v.x, v.y);
    }
    __syncthreads();

    for (int tile = blockIdx.x; tile < GT_TILES; tile += gridDim.x) {
        const size_t mBase = (size_t)tile * 128;
        for (int i = tid; i < 128 * 64; i += XP_THREADS) {
            int m = i >> 6, kw = i & 63;
            float2 v = *reinterpret_cast<const float2*>(&g_h1[(mBase + m) * HH + kw * 2]);
            As[m * AST + kw] = cvt_bf2(v.x, v.y);
        }
        __syncthreads();

        const int r0 = wid * 16 + l4;
        const unsigned* Ar0 = As + r0 * AST;
        const unsigned* Ar1 = As + (r0 + 8) * AST;
        const size_t gm0 = (mBase + r0) * GG;
        const size_t gm1 = (mBase + r0 + 8) * GG;

        #pragma unroll 1
        for (int nc = 0; nc < 8; ++nc) {
            float acc[8][4];
            #pragma unroll
            for (int nt = 0; nt < 8; ++nt)
                #pragma unroll
                for (int q = 0; q < 4; ++q) acc[nt][q] = 0.0f;

            #pragma unroll
            for (int ks = 0; ks < 8; ++ks) {
                const int kb = ks * 8 + l2;
                unsigned a0 = Ar0[kb], a1 = Ar1[kb];
                unsigned a2 = Ar0[kb + 4], a3 = Ar1[kb + 4];
                #pragma unroll
                for (int nt = 0; nt < 8; ++nt) {
                    const unsigned* Bn = Bs + (nc * 64 + nt * 8 + l4) * BST;
                    mma16816(acc[nt], a0, a1, a2, a3, Bn[kb], Bn[kb + 4]);
                }
            }
            #pragma unroll
            for (int nt = 0; nt < 8; ++nt) {
                const int nb = nc * 64 + nt * 8 + l2 * 2;
                float b0 = bias[nb], b1 = bias[nb + 1];
                *reinterpret_cast<float2*>(&g_xp1[gm0 + nb]) =
                    make_float2(acc[nt][0] + b0, acc[nt][1] + b1);
                *reinterpret_cast<float2*>(&g_xp1[gm1 + nb]) =
                    make_float2(acc[nt][2] + b0, acc[nt][3] + b1);
            }
        }
        __syncthreads();
    }
}

// =========== unified LSTM recurrence on tensor cores (mma.sync) ===========
// 32 CTAs x 16 batches; per step one M=16 x N=512 x K=128 bf16 GEMM.
// mode 0: write h to g_h1 each step. mode 1: fused FC head at the end.
#define MB    16
#define RCTA  (BB / MB)                 // 32
#define RB_OFF 0                        // Whh bf16x2 [512][68] = 139264 B
#define RA_OFF (512 * 68 * 4)           // h bf16x2 [16][68]    = 4352 B
#define RG_OFF (RA_OFF + 16 * 68 * 4)   // gates f32 [16][516]  = 33024 B
#define R_SMEM (RG_OFF + 16 * 516 * 4)  // 176640 B

__global__ void __launch_bounds__(512, 1)
lstm_rec(const float* __restrict__ xp, const float* __restrict__ Whh,
         float* __restrict__ h_out, int mode,
         const float* __restrict__ Wfc1, const float* __restrict__ bfc1,
         const float* __restrict__ Wfc2, const float* __restrict__ bfc2,
         float* __restrict__ out)
{
    extern __shared__ char smem[];
    unsigned* Bw = reinterpret_cast<unsigned*>(smem + RB_OFF);
    unsigned* Aw = reinterpret_cast<unsigned*>(smem + RA_OFF);
    float*    Gt = reinterpret_cast<float*>(smem + RG_OFF);
    const int tid  = threadIdx.x;
    const int wid  = tid >> 5, lane = tid & 31;
    const int l4   = lane >> 2, l2 = lane & 3;
    const int bb   = blockIdx.x * MB;

    // Whh [512][128] f32 -> Bw [n][kword] bf16x2, stride 68 (conflict-free)
    for (int i = tid; i < GG * 64; i += 512) {
        int n = i >> 6, kw = i & 63;
        float2 v = *reinterpret_cast<const float2*>(&Whh[(size_t)n * HH + kw * 2]);
        Bw[n * 68 + kw] = cvt_bf2(v.x, v.y);
    }
    for (int i = tid; i < MB * 68; i += 512) Aw[i] = 0u;   // h(0) = 0
    __syncthreads();

    // cell-update assignment: thread owns (u = tid&127, batches bq+4j)
    const int uu = tid & 127;
    const int bq = tid >> 7;
    float cst[4] = {0.f, 0.f, 0.f, 0.f};

    const unsigned* Ar0 = Aw + l4 * 68;
    const unsigned* Ar1 = Aw + (l4 + 8) * 68;
    const int nb0 = wid * 32;            // warp's 32-gate stripe

    for (int t = 0; t < TT; ++t) {
        // prefetch xp (consumed after the mma — latency hidden)
        float xpr[16];
        #pragma unroll
        for (int j = 0; j < 4; ++j) {
            const float* xr = &xp[((size_t)(bb + bq + 4 * j) * TT + t) * GG + uu];
            xpr[j * 4 + 0] = xr[0];
            xpr[j * 4 + 1] = xr[128];
            xpr[j * 4 + 2] = xr[256];
            xpr[j * 4 + 3] = xr[384];
        }

        float acc[4][4];
        #pragma unroll
        for (int nt = 0; nt < 4; ++nt)
            #pragma unroll
            for (int q = 0; q < 4; ++q) acc[nt][q] = 0.0f;

        #pragma unroll
        for (int ks = 0; ks < 8; ++ks) {
            const int kb = ks * 8 + l2;
            unsigned a0 = Ar0[kb], a1 = Ar1[kb];
            unsigned a2 = Ar0[kb + 4], a3 = Ar1[kb + 4];
            #pragma unroll
            for (int nt = 0; nt < 4; ++nt) {
                const unsigned* Bn = Bw + (nb0 + nt * 8 + l4) * 68;
                mma16816(acc[nt], a0, a1, a2, a3, Bn[kb], Bn[kb + 4]);
            }
        }

        // D frags -> gate buffer [batch][gate]
        #pragma unroll
        for (int nt = 0; nt < 4; ++nt) {
            const int col = nb0 + nt * 8 + l2 * 2;
            *reinterpret_cast<float2*>(&Gt[l4 * 516 + col]) =
                make_float2(acc[nt][0], acc[nt][1]);
            *reinterpret_cast<float2*>(&Gt[(l4 + 8) * 516 + col]) =
                make_float2(acc[nt][2], acc[nt][3]);
        }
        __syncthreads();   // gates visible; also orders A reads before h rewrite

        #pragma unroll
        for (int j = 0; j < 4; ++j) {
            const int b = bq + 4 * j;
            float zi = Gt[b * 516 + uu]       + xpr[j * 4 + 0];
            float zf = Gt[b * 516 + 128 + uu] + xpr[j * 4 + 1];
            float zg = Gt[b * 516 + 256 + uu] + xpr[j * 4 + 2];
            float zo = Gt[b * 516 + 384 + uu] + xpr[j * 4 + 3];
            float ig = sig_hw(zi), fg = sig_hw(zf), cg = tanh_hw(zg), og = sig_hw(zo);
            cst[j] = __fmaf_rn(fg, cst[j], ig * cg);
            float hv = og * tanh_hw(cst[j]);
            reinterpret_cast<__nv_bfloat16*>(Aw)[b * 136 + uu] = __float2bfloat16(hv);
            if (mode == 0)
                h_out[((size_t)(bb + b) * TT + t) * HH + uu] = hv;
            else if (t == TT - 1)
                Gt[b * 516 + uu] = hv;   // stash f32 h for FC (own slot only)
        }
        __syncthreads();   // h(t+1) tile ready
    }

    if (mode == 1) {
        // FC head: warp wid handles batch wid; lane computes 2 fc1 units
        float sum = 0.0f;
        #pragma unroll
        for (int jj = 0; jj < 2; ++jj) {
            const int jn = lane * 2 + jj;
            float accf = bfc1[jn];
            const float* wr = &Wfc1[jn * HH];
            #pragma unroll 8
            for (int k = 0; k < HH; ++k)
                accf = __fmaf_rn(Gt[wid * 516 + k], wr[k], accf);
            sum += fmaxf(accf, 0.0f) * Wfc2[jn];
        }
        #pragma unroll
        for (int off = 16; off > 0; off >>= 1)
            sum += __shfl_down_sync(0xFFFFFFFFu, sum, off);
        if (lane == 0)
            out[bb + wid] = sig_exact(sum + bfc2[0]);
    }
}

extern "C" void kernel_launch(void* const* d_in, const int* in_sizes, int n_in,
                              void* d_out, int out_size)
{
    const float* x     = (const float*)d_in[0];
    const float* Wih0  = (const float*)d_in[1];
    const float* Whh0  = (const float*)d_in[2];
    const float* bih0  = (const float*)d_in[3];
    const float* bhh0  = (const float*)d_in[4];
    const float* Wih1  = (const float*)d_in[5];
    const float* Whh1  = (const float*)d_in[6];
    const float* bih1  = (const float*)d_in[7];
    const float* bhh1  = (const float*)d_in[8];
    const float* Wfc1  = (const float*)d_in[9];
    const float* bfc1  = (const float*)d_in[10];
    const float* Wfc2  = (const float*)d_in[11];
    const float* bfc2  = (const float*)d_in[12];
    float* out = (float*)d_out;

    float* d_h1;  cudaGetSymbolAddress((void**)&d_h1, g_h1);
    float* d_xp0; cudaGetSymbolAddress((void**)&d_xp0, g_xp0);
    float* d_xp1; cudaGetSymbolAddress((void**)&d_xp1, g_xp1);

    static bool attr_done = false;
    if (!attr_done) {
        cudaFuncSetAttribute(xproj0_mma, cudaFuncAttributeMaxDynamicSharedMemorySize, X0_SMEM);
        cudaFuncSetAttribute(xproj1_mma, cudaFuncAttributeMaxDynamicSharedMemorySize, XP_SMEM);
        cudaFuncSetAttribute(lstm_rec,   cudaFuncAttributeMaxDynamicSharedMemorySize, R_SMEM);
        attr_done = true;
    }

    xproj0_mma<<<148, 256, X0_SMEM>>>(x, Wih0, bih0, bhh0);
    lstm_rec<<<RCTA, 512, R_SMEM>>>(d_xp0, Whh0, d_h1, 0,
                                    Wfc1, bfc1, Wfc2, bfc2, out);
    xproj1_mma<<<148, XP_THREADS, XP_SMEM>>>(Wih1, bih1, bhh1);
    lstm_rec<<<RCTA, 512, R_SMEM>>>(d_xp1, Whh1, nullptr, 1,
                                    Wfc1, bfc1, Wfc2, bfc2, out);
}